// round 2
// baseline (speedup 1.0000x reference)
#include <cuda_runtime.h>
#include <math.h>

#define DDIM   512
#define KCODES 1024
#define BM 128
#define BN 128
#define BK 16
#define ASTR 132   // padded row stride (floats) for smem tiles

// ---- device-global scratch (allowed; no runtime allocation) ----
__device__ float        g_cnorm[KCODES];
__device__ unsigned int g_hist[KCODES];
__device__ double       g_sumsq;

// ============================================================
// Prep: codebook squared norms (double-accurate, f32 result) +
// zero accumulators (every launch; graph replays rerun sequence)
// ============================================================
__global__ void vq_prep(const float* __restrict__ cb) {
    int k = blockIdx.x;          // one block per code
    int t = threadIdx.x;         // 128 threads
    const float4* row = (const float4*)(cb + (size_t)k * DDIM);
    float4 q = row[t];           // 128 float4 = 512 floats
    // ref: fl(c*c) elementwise, then reduce; we reduce in double (<=0.5ulp)
    double v = (double)__fmul_rn(q.x,q.x) + (double)__fmul_rn(q.y,q.y)
             + (double)__fmul_rn(q.z,q.z) + (double)__fmul_rn(q.w,q.w);
    #pragma unroll
    for (int off = 16; off; off >>= 1) v += __shfl_down_sync(0xFFFFFFFFu, v, off);
    __shared__ double ws[4];
    if ((t & 31) == 0) ws[t >> 5] = v;
    __syncthreads();
    if (t == 0) {
        g_cnorm[k] = (float)(ws[0] + ws[1] + ws[2] + ws[3]);
        g_hist[k]  = 0u;
        if (k == 0) g_sumsq = 0.0;
    }
}

// ============================================================
// Main: fused SGEMM (ascending-k single-acc FMA chain == cublas) +
// reference-faithful score rounding + per-row argmin (first-index
// tie-break) + quantized write + loss partial + histogram.
// ============================================================
__global__ __launch_bounds__(256)
void vq_main(const float* __restrict__ in, const float* __restrict__ cb,
             float* __restrict__ out, int nrows) {
    __shared__ float As[BK * ASTR];      // [dd][row]  (transposed)
    __shared__ float Bs[BK * ASTR];      // [dd][col]
    __shared__ float cn_s[KCODES];
    __shared__ float rs_s[BM];
    __shared__ int   idx_s[BM];
    __shared__ float red_s[8];

    const int tid = threadIdx.x;
    const int tx  = tid & 15;            // 0..15 -> 8 cols each
    const int ty  = tid >> 4;            // 0..15 -> 8 rows each
    const int rowBase = blockIdx.x * BM;

    for (int i = tid; i < KCODES; i += 256) cn_s[i] = g_cnorm[i];

    // per-row squared norms, double-accurate then rounded to f32.
    // (whole-ulp deviations vs ref's own f32 reduction shift the whole
    //  row's score lattice uniformly -> argmin invariant)
    if (tid < BM) {
        const float4* rp = (const float4*)(in + (size_t)(rowBase + tid) * DDIM);
        double s = 0.0;
        #pragma unroll 8
        for (int i = 0; i < DDIM / 4; i++) {
            float4 v = rp[i];
            s += (double)__fmul_rn(v.x,v.x) + (double)__fmul_rn(v.y,v.y)
               + (double)__fmul_rn(v.z,v.z) + (double)__fmul_rn(v.w,v.w);
        }
        rs_s[tid] = (float)s;
    }
    __syncthreads();

    float bestV[8];
    int   bestI[8];
    #pragma unroll
    for (int i = 0; i < 8; i++) { bestV[i] = 3.4e38f; bestI[i] = 0x7FFFFFFF; }

    for (int kc0 = 0; kc0 < KCODES; kc0 += BN) {
        float acc[8][8];
        #pragma unroll
        for (int i = 0; i < 8; i++)
            #pragma unroll
            for (int j = 0; j < 8; j++) acc[i][j] = 0.f;

        for (int d0 = 0; d0 < DDIM; d0 += BK) {
            // stage A (input rows) and B (codebook rows), transposed to [dd][m]
            #pragma unroll
            for (int p = 0; p < 2; p++) {
                int id = tid + p * 256;          // 0..511
                int r  = id >> 2;                // 0..127
                int c4 = id & 3;                 // float4 slot within 16 d's
                float4 va = *(const float4*)(in + (size_t)(rowBase + r) * DDIM + d0 + c4 * 4);
                As[(c4*4+0)*ASTR + r] = va.x;
                As[(c4*4+1)*ASTR + r] = va.y;
                As[(c4*4+2)*ASTR + r] = va.z;
                As[(c4*4+3)*ASTR + r] = va.w;
                float4 vb = *(const float4*)(cb + (size_t)(kc0 + r) * DDIM + d0 + c4 * 4);
                Bs[(c4*4+0)*ASTR + r] = vb.x;
                Bs[(c4*4+1)*ASTR + r] = vb.y;
                Bs[(c4*4+2)*ASTR + r] = vb.z;
                Bs[(c4*4+3)*ASTR + r] = vb.w;
            }
            __syncthreads();
            // strictly ascending k, one accumulator per output element:
            // identical rounding chain to cublas/Eigen SGEMM.
            #pragma unroll
            for (int kk = 0; kk < BK; kk++) {
                float4 a0 = *(const float4*)&As[kk*ASTR + ty*8];
                float4 a1 = *(const float4*)&As[kk*ASTR + ty*8 + 4];
                float4 b0 = *(const float4*)&Bs[kk*ASTR + tx*8];
                float4 b1 = *(const float4*)&Bs[kk*ASTR + tx*8 + 4];
                float a[8] = {a0.x,a0.y,a0.z,a0.w,a1.x,a1.y,a1.z,a1.w};
                float b[8] = {b0.x,b0.y,b0.z,b0.w,b1.x,b1.y,b1.z,b1.w};
                #pragma unroll
                for (int i = 0; i < 8; i++)
                    #pragma unroll
                    for (int j = 0; j < 8; j++)
                        acc[i][j] = fmaf(a[i], b[j], acc[i][j]);
            }
            __syncthreads();
        }

        // Reference-faithful score: fl(fl(rs + cn) - 2*m), NO fma contraction.
        // Ascending column order + strict '<' => first index on ties,
        // matching jnp.argmin on the same rounded lattice values.
        #pragma unroll
        for (int i = 0; i < 8; i++) {
            float rsv = rs_s[ty * 8 + i];
            float bv = 3.4e38f; int bi = 0x7FFFFFFF;
            #pragma unroll
            for (int j = 0; j < 8; j++) {
                int col = kc0 + tx * 8 + j;
                float s = __fsub_rn(__fadd_rn(rsv, cn_s[col]),
                                    __fmul_rn(2.0f, acc[i][j]));
                if (s < bv) { bv = s; bi = col; }
            }
            #pragma unroll
            for (int off = 1; off < 16; off <<= 1) {
                float ov = __shfl_xor_sync(0xFFFFFFFFu, bv, off);
                int   oi = __shfl_xor_sync(0xFFFFFFFFu, bi, off);
                if (ov < bv || (ov == bv && oi < bi)) { bv = ov; bi = oi; }
            }
            if (bv < bestV[i] || (bv == bestV[i] && bi < bestI[i])) {
                bestV[i] = bv; bestI[i] = bi;
            }
        }
    }

    if (tx == 0) {
        #pragma unroll
        for (int i = 0; i < 8; i++) idx_s[ty * 8 + i] = bestI[i];
    }
    __syncthreads();

    if (tid < BM) atomicAdd(&g_hist[idx_s[tid]], 1u);

    // quantized write (d_out+1 is only 4B-aligned -> scalar, coalesced)
    // + loss partial sum
    float local = 0.f;
    #pragma unroll 4
    for (int e = tid; e < BM * DDIM; e += 256) {
        int r = e >> 9;           // /512
        int c = e & 511;
        int idx = idx_s[r];
        float q = cb[(size_t)idx * DDIM + c];
        float x = in[(size_t)(rowBase + r) * DDIM + c];
        out[1 + (size_t)(rowBase + r) * DDIM + c] = q;
        float d = q - x;
        local = fmaf(d, d, local);
    }
    #pragma unroll
    for (int off = 16; off; off >>= 1) local += __shfl_down_sync(0xFFFFFFFFu, local, off);
    if ((tid & 31) == 0) red_s[tid >> 5] = local;
    __syncthreads();
    if (tid == 0) {
        float s = 0.f;
        #pragma unroll
        for (int w = 0; w < 8; w++) s += red_s[w];
        atomicAdd(&g_sumsq, (double)s);
    }
}

// ============================================================
// Finalize: loss + perplexity scalars
// ============================================================
__global__ void vq_final(float* __restrict__ out, int out_size, int nrows) {
    int t = threadIdx.x;                 // 1024 == KCODES
    double p = (double)g_hist[t] / (double)nrows;
    double term = p * log(p + 1e-10);
    #pragma unroll
    for (int off = 16; off; off >>= 1) term += __shfl_down_sync(0xFFFFFFFFu, term, off);
    __shared__ double ws[32];
    if ((t & 31) == 0) ws[t >> 5] = term;
    __syncthreads();
    if (t == 0) {
        double s = 0.0;
        #pragma unroll
        for (int w = 0; w < 32; w++) s += ws[w];
        double mean = g_sumsq / ((double)nrows * (double)DDIM);
        out[0] = (float)(1.25 * mean);            // q_loss + 0.25*e_loss
        out[out_size - 1] = (float)exp(-s);       // perplexity
    }
}

// ============================================================
extern "C" void kernel_launch(void* const* d_in, const int* in_sizes, int n_in,
                              void* d_out, int out_size) {
    const float* inputs = (const float*)d_in[0];
    const float* cb     = (const float*)d_in[1];
    float* out = (float*)d_out;
    int nrows = in_sizes[0] / DDIM;      // 65536

    vq_prep<<<KCODES, 128>>>(cb);
    vq_main<<<nrows / BM, 256>>>(inputs, cb, out, nrows);
    vq_final<<<1, KCODES>>>(out, out_size, nrows);
}